// round 13
// baseline (speedup 1.0000x reference)
#include <cuda_runtime.h>
#include <cuda_bf16.h>
#include <cuda_fp16.h>
#include <cstdint>

#define TT 512
#define BB 64
#define HH 512
#define II 1024

// ---- scratch ---------------------------------------------------------------
__device__ float g_xproj[2][(size_t)TT * BB * HH];
__device__ float g_l0out[(size_t)TT * BB * 2 * HH];
__device__ unsigned g_flags[2][4][16][4][8];   // [dir][bg][hg][warp], 32B apart
// proj operands: pre-swizzled fp16 blocks (128 rows x 64 k = 16384B)
__device__ char g_ahi[(size_t)2 * 256 * 16 * 16384];          // A fp16 (single plane)
__device__ char g_whi[(size_t)4 * 4 * 16 * 16384];            // W_ih fp16 hi
__device__ char g_wlo[(size_t)4 * 4 * 16 * 16384];            // W_ih fp16 lo
// recurrence: W_hh bf16 pre-swizzled blocks (16 rows x 64 k = 2048B, 8 chunks)
__device__ char g_whh_hi[(size_t)4 * 32 * 16384];
__device__ char g_whh_lo[(size_t)4 * 32 * 16384];
// h*noise: [dir*2+pp][bg] 32KB block = [kc 8][plane 2][16b x 128B swizzled]
__device__ char g_hn2[(size_t)4 * 4 * 32768];

// ---- helpers ---------------------------------------------------------------
__device__ __forceinline__ unsigned ld_acq(const unsigned* p) {
    unsigned v;
    asm volatile("ld.acquire.gpu.global.u32 %0, [%1];" : "=r"(v) : "l"(p) : "memory");
    return v;
}
__device__ __forceinline__ void st_rel(unsigned* p, unsigned v) {
    asm volatile("st.release.gpu.global.u32 [%0], %1;" :: "l"(p), "r"(v) : "memory");
}
__device__ __forceinline__ float my_tanhf(float x) {
    float e = __expf(2.f * x);
    return 1.f - 2.f / (e + 1.f);
}
__device__ __forceinline__ uint32_t smem_to_u32(const void* p) {
    uint32_t a;
    asm("{ .reg .u64 t; cvta.to.shared.u64 t, %1; cvt.u32.u64 %0, t; }" : "=r"(a) : "l"(p));
    return a;
}
#define CP_ASYNC16(dst, src) \
    asm volatile("cp.async.cg.shared.global [%0], [%1], 16;" :: "r"(dst), "l"(src))
#define CP_COMMIT() asm volatile("cp.async.commit_group;" ::: "memory")
#define CP_WAIT(N)  asm volatile("cp.async.wait_group %0;" :: "n"(N) : "memory")
#define SMEM_SWZ(off) ((off) ^ (((off) >> 3) & 0x70))
#define LDSM_X4(r0, r1, r2, r3, a) \
    asm volatile("ldmatrix.sync.aligned.m8n8.x4.shared.b16 {%0,%1,%2,%3}, [%4];" \
        : "=r"(r0), "=r"(r1), "=r"(r2), "=r"(r3) : "r"(a))
#define MMA16816(c, a, b0, b1) \
    asm volatile("mma.sync.aligned.m16n8k16.row.col.f32.bf16.bf16.f32 " \
        "{%0,%1,%2,%3}, {%4,%5,%6,%7}, {%8,%9}, {%0,%1,%2,%3};" \
        : "+f"((c)[0]), "+f"((c)[1]), "+f"((c)[2]), "+f"((c)[3]) \
        : "r"((a)[0]), "r"((a)[1]), "r"((a)[2]), "r"((a)[3]), "r"(b0), "r"(b1))
#define MMA16816H(c, a, b0, b1) \
    asm volatile("mma.sync.aligned.m16n8k16.row.col.f32.f16.f16.f32 " \
        "{%0,%1,%2,%3}, {%4,%5,%6,%7}, {%8,%9}, {%0,%1,%2,%3};" \
        : "+f"((c)[0]), "+f"((c)[1]), "+f"((c)[2]), "+f"((c)[3]) \
        : "r"((a)[0]), "r"((a)[1]), "r"((a)[2]), "r"((a)[3]), "r"(b0), "r"(b1))

// ---------------------------------------------------------------------------
// Merged weight conversion + flag reset. Blocks [0,2048) = W_ih fp16 hi/lo,
// [2048,3072) = W_hh bf16 hi/lo. Block 0 also zeroes the rnn flags.
__global__ __launch_bounds__(256) void conv_kernel(
    const float* __restrict__ w_ih, const float* __restrict__ w_hh)
{
    if (blockIdx.x == 0) {
        // 2*4*16*4 = 512 flags, stride 8 words
        ((unsigned*)g_flags)[threadIdx.x * 8] = 0u;
        ((unsigned*)g_flags)[(threadIdx.x + 256) * 8] = 0u;
    }
    if (blockIdx.x < 2048) {
        int e0 = (blockIdx.x * 256 + threadIdx.x) * 4;
        int cell = e0 >> 19;
        int rem  = e0 & 524287;
        int h = rem >> 10;
        int k = rem & 1023;
        float4 v = *(const float4*)(w_ih + (size_t)e0);
        __half h0 = __float2half(v.x), h1 = __float2half(v.y);
        __half h2 = __float2half(v.z), h3 = __float2half(v.w);
        __half l0 = __float2half(v.x - __half2float(h0));
        __half l1 = __float2half(v.y - __half2float(h1));
        __half l2 = __float2half(v.z - __half2float(h2));
        __half l3 = __float2half(v.w - __half2float(h3));
        int nb = h >> 7, hr = h & 127, kc = k >> 6, kk = k & 63;
        int sw = SMEM_SWZ(hr * 128 + kk * 2);
        size_t base = ((size_t)(cell * 4 + nb) * 16 + kc) * 16384 + sw;
        __half2 p;
        p.x = h0; p.y = h1; *(__half2*)(g_whi + base) = p;
        p.x = h2; p.y = h3; *(__half2*)(g_whi + base + 4) = p;
        p.x = l0; p.y = l1; *(__half2*)(g_wlo + base) = p;
        p.x = l2; p.y = l3; *(__half2*)(g_wlo + base + 4) = p;
    } else {
        int e0 = ((blockIdx.x - 2048) * 256 + threadIdx.x) * 4;
        int cell = e0 >> 18;
        int rem  = e0 & 262143;
        int h = rem >> 9;
        int k = rem & 511;
        float4 v = *(const float4*)(w_hh + (size_t)e0);
        __nv_bfloat16 h0 = __float2bfloat16(v.x), h1 = __float2bfloat16(v.y);
        __nv_bfloat16 h2 = __float2bfloat16(v.z), h3 = __float2bfloat16(v.w);
        __nv_bfloat16 l0 = __float2bfloat16(v.x - __bfloat162float(h0));
        __nv_bfloat16 l1 = __float2bfloat16(v.y - __bfloat162float(h1));
        __nv_bfloat16 l2 = __float2bfloat16(v.z - __bfloat162float(h2));
        __nv_bfloat16 l3 = __float2bfloat16(v.w - __bfloat162float(h3));
        int hg = h >> 4, r = h & 15, kc = k >> 6, kk = k & 63;
        size_t base = (size_t)(cell * 32 + hg) * 16384 + kc * 2048 + SMEM_SWZ(r * 128 + kk * 2);
        __nv_bfloat162 p;
        p.x = h0; p.y = h1; *(__nv_bfloat162*)(g_whh_hi + base) = p;
        p.x = h2; p.y = h3; *(__nv_bfloat162*)(g_whh_hi + base + 4) = p;
        p.x = l0; p.y = l1; *(__nv_bfloat162*)(g_whh_lo + base) = p;
        p.x = l2; p.y = l3; *(__nv_bfloat162*)(g_whh_lo + base + 4) = p;
    }
}

// ---------------------------------------------------------------------------
// A -> fp16 pre-swizzled blocks, both dirs per block (A read once).
__global__ __launch_bounds__(256) void aconv_kernel(
    const float* __restrict__ Ain, const float* __restrict__ nin, int layer)
{
    const float* A = (layer == 0) ? Ain : g_l0out;
    int e0 = (blockIdx.x * 256 + threadIdx.x) * 4;
    int m = e0 >> 10;
    int k = e0 & 1023;
    float4 a = *(const float4*)(A + (size_t)e0);
    int mb = m >> 7, mr = m & 127, kc = k >> 6, kk = k & 63;
    int sw = SMEM_SWZ(mr * 128 + kk * 2);
#pragma unroll
    for (int dir = 0; dir < 2; dir++) {
        int cell = layer * 2 + dir;
        float4 n = *(const float4*)(nin + (size_t)cell * BB * II + (m & 63) * II + k);
        __half2 p0, p1;
        p0.x = __float2half(a.x * n.x); p0.y = __float2half(a.y * n.y);
        p1.x = __float2half(a.z * n.z); p1.y = __float2half(a.w * n.w);
        size_t base = ((size_t)(dir * 256 + mb) * 16 + kc) * 16384 + sw;
        *(__half2*)(g_ahi + base) = p0;
        *(__half2*)(g_ahi + base + 4) = p1;
    }
}

// ---------------------------------------------------------------------------
// proj via mma.sync fp16 2-term (unchanged R12 winner).
#define PROJ_SMEM 98304

#define PROJ_ISSUE(c) do { \
    uint32_t st = smb + ((c) & 1) * 49152 + tid * 16; \
    size_t go = (size_t)(c) * 16384 + tid * 16; \
    _Pragma("unroll") \
    for (int p = 0; p < 4; p++) { \
        CP_ASYNC16(st +     0 + p * 4096, srcAh + go + p * 4096); \
        CP_ASYNC16(st + 16384 + p * 4096, srcBh + go + p * 4096); \
        CP_ASYNC16(st + 32768 + p * 4096, srcBl + go + p * 4096); \
    } \
    CP_COMMIT(); \
} while (0)

__global__ __launch_bounds__(256, 1) void proj_mma_kernel(
    const float* __restrict__ b_ih, int layer)
{
    extern __shared__ char smc[];
    uint32_t smb = smem_to_u32(smc);
    int tid = threadIdx.x, lane = tid & 31, warp = tid >> 5;
    int nb = blockIdx.x, mb = blockIdx.y, dir = blockIdx.z;
    int cell = layer * 2 + dir;
    const char* srcAh = g_ahi + (size_t)(dir * 256 + mb) * 16 * 16384;
    const char* srcBh = g_whi + (size_t)(cell * 4 + nb) * 16 * 16384;
    const char* srcBl = g_wlo + (size_t)(cell * 4 + nb) * 16 * 16384;

    float acc[2][8][4];
#pragma unroll
    for (int i = 0; i < 2; i++)
#pragma unroll
        for (int j = 0; j < 8; j++)
#pragma unroll
            for (int q = 0; q < 4; q++) acc[i][j][q] = 0.f;

    int wm = (warp >> 1) * 32;
    int wn = (warp & 1) * 64;
    int ar  = wm + (lane & 15);
    int ac0 = (lane >> 4) << 4;
    int br  = wn + ((lane >> 4) << 3) + (lane & 7);
    int bc0 = ((lane >> 3) & 1) << 4;

    PROJ_ISSUE(0);
    for (int c = 0; c < 16; c++) {
        if (c + 1 < 16) { PROJ_ISSUE(c + 1); CP_WAIT(1); }
        else CP_WAIT(0);
        __syncthreads();
        uint32_t st = smb + (c & 1) * 49152;
#pragma unroll
        for (int ks = 0; ks < 4; ks++) {
            int acol = ks * 32 + ac0;
            int bcol = ks * 32 + bc0;
            uint32_t ah[2][4];
            LDSM_X4(ah[0][0], ah[0][1], ah[0][2], ah[0][3], st + SMEM_SWZ(ar * 128 + acol));
            LDSM_X4(ah[1][0], ah[1][1], ah[1][2], ah[1][3], st + SMEM_SWZ((ar + 16) * 128 + acol));
            uint32_t bh[4][4], bl[4][4];
#pragma unroll
            for (int j = 0; j < 4; j++) {
                LDSM_X4(bh[j][0], bh[j][1], bh[j][2], bh[j][3],
                        st + 16384 + SMEM_SWZ((br + j * 16) * 128 + bcol));
                LDSM_X4(bl[j][0], bl[j][1], bl[j][2], bl[j][3],
                        st + 32768 + SMEM_SWZ((br + j * 16) * 128 + bcol));
            }
#pragma unroll
            for (int mt = 0; mt < 2; mt++)
#pragma unroll
                for (int j = 0; j < 4; j++) {
                    MMA16816H(acc[mt][2 * j],     ah[mt], bh[j][0], bh[j][1]);
                    MMA16816H(acc[mt][2 * j],     ah[mt], bl[j][0], bl[j][1]);
                    MMA16816H(acc[mt][2 * j + 1], ah[mt], bh[j][2], bh[j][3]);
                    MMA16816H(acc[mt][2 * j + 1], ah[mt], bl[j][2], bl[j][3]);
                }
        }
        __syncthreads();
    }

    const float* bias = b_ih + (size_t)cell * HH;
    float* out = g_xproj[dir];
    int g  = lane >> 2;
    int tq = (lane & 3) * 2;
    int m0 = mb * 128 + wm;
    int n0 = nb * 128 + wn;
#pragma unroll
    for (int mt = 0; mt < 2; mt++)
#pragma unroll
        for (int nt = 0; nt < 8; nt++) {
            int h = n0 + nt * 8 + tq;
            float2 bi = *(const float2*)(bias + h);
            int m = m0 + mt * 16 + g;
            float2 v;
            v.x = acc[mt][nt][0] + bi.x; v.y = acc[mt][nt][1] + bi.y;
            *(float2*)(out + (size_t)m * HH + h) = v;
            v.x = acc[mt][nt][2] + bi.x; v.y = acc[mt][nt][3] + bi.y;
            *(float2*)(out + (size_t)(m + 8) * HH + h) = v;
        }
}

// ---------------------------------------------------------------------------
// Persistent recurrence. Per-warp flags + all-warp polling + double-buffered
// staging: 2 block barriers per step (down from 4).
// smem: stage 2x32KB @0 | W hi 32KB @65536 | W lo 32KB @98304
#define RNN_SMEM 131072

__global__ __launch_bounds__(128, 1) void rnn_mma_kernel(
    const float* __restrict__ b_hh, const float* __restrict__ noise_h,
    const float* __restrict__ mask, float* __restrict__ dout, int layer)
{
    extern __shared__ char smc[];
    uint32_t smb = smem_to_u32(smc);
    int tid = threadIdx.x, lane = tid & 31, warp = tid >> 5;   // warp 0..3
    int hg = blockIdx.x, bg = blockIdx.y, dir = blockIdx.z;
    int cell = layer * 2 + dir;
    unsigned fbase = (unsigned)(layer << 9);
    float* ys = (layer == 0) ? g_l0out : dout;
    const float* xproj = g_xproj[dir];

    // one-time: resident W_hh hi/lo
    {
        const char* wsh = g_whh_hi + (size_t)(cell * 32 + hg * 2) * 16384;
        const char* wsl = g_whh_lo + (size_t)(cell * 32 + hg * 2) * 16384;
#pragma unroll
        for (int i = 0; i < 16; i++) {
            CP_ASYNC16(smb + 65536 + tid * 16 + i * 2048, wsh + tid * 16 + i * 2048);
            CP_ASYNC16(smb + 98304 + tid * 16 + i * 2048, wsl + tid * 16 + i * 2048);
        }
        CP_COMMIT();
        CP_WAIT(0);
        __syncthreads();
    }

    int g  = lane >> 2;
    int tq = (lane & 3) * 2;
    int b0l = g, b1l = g + 8;
    int b0 = bg * 16 + b0l, b1 = bg * 16 + b1l;
    int hl32 = warp * 8 + tq;
    int h0 = hg * 32 + hl32;

    float2 bias2 = *(const float2*)(b_hh + (size_t)cell * HH + h0);
    float2 nh0 = *(const float2*)(noise_h + ((size_t)cell * BB + b0) * HH + h0);
    float2 nh1 = *(const float2*)(noise_h + ((size_t)cell * BB + b1) * HH + h0);
    float hp[4] = {0.f, 0.f, 0.f, 0.f};

    int arow = lane & 15;
    int ac0  = (lane >> 4) << 4;
    int brow = (warp & 1) * 8 + (lane & 7);
    int bj   = (lane >> 3) << 4;
    uint32_t wb_hi = smb + 65536 + (warp >> 1) * 16384;
    uint32_t wb_lo = wb_hi + 32768;

    int hl64 = (hg & 1) * 32 + hl32;
    uint32_t o0 = SMEM_SWZ(b0l * 128 + hl64 * 2);
    uint32_t o1 = SMEM_SWZ(b1l * 128 + hl64 * 2);

    // this warp's poll targets: 2 of the 64 (hg, warp) flags
    const unsigned* fpA = &g_flags[dir][bg][lane & 15][lane >> 4][0];
    const unsigned* fpB = &g_flags[dir][bg][lane & 15][(lane >> 4) + 2][0];

    for (int s = 0; s < TT; s++) {
        int t = dir ? (TT - 1 - s) : s;
        float2 xp0 = *(const float2*)(xproj + ((size_t)t * BB + b0) * HH + h0);
        float2 xp1 = *(const float2*)(xproj + ((size_t)t * BB + b1) * HH + h0);
        float mA = mask[t * BB + b0];
        float mB = mask[t * BB + b1];

        float acc[4] = {0.f, 0.f, 0.f, 0.f};

        if (s > 0) {
            // every warp polls all 64 producer-warp flags (2 per lane)
            unsigned tgt = fbase + (unsigned)s;
            unsigned vA, vB;
            do { vA = ld_acq(fpA); vB = ld_acq(fpB); }
            while (!__all_sync(0xffffffffu, (vA >= tgt) && (vB >= tgt)));

            const char* src = g_hn2 + ((size_t)(dir * 2 + ((s + 1) & 1)) * 4 + bg) * 32768;
            uint32_t sbuf = smb + (s & 1) * 32768;
#pragma unroll
            for (int i = 0; i < 8; i++)
                CP_ASYNC16(sbuf + tid * 16 + i * 2048, src + tid * 16 + i * 2048);
            CP_COMMIT();
#pragma unroll
            for (int i = 8; i < 16; i++)
                CP_ASYNC16(sbuf + tid * 16 + i * 2048, src + tid * 16 + i * 2048);
            CP_COMMIT();

#pragma unroll
            for (int gp = 0; gp < 2; gp++) {
                if (gp == 0) CP_WAIT(1);
                else CP_WAIT(0);
                __syncthreads();
#pragma unroll
                for (int ci = 0; ci < 4; ci++) {
                    int kc = gp * 4 + ci;
                    uint32_t hnHi = sbuf + kc * 4096;
                    uint32_t hnLo = hnHi + 2048;
                    uint32_t wHi  = wb_hi + kc * 2048;
                    uint32_t wLo  = wb_lo + kc * 2048;
                    uint32_t bh[2][4], bl[2][4];
#pragma unroll
                    for (int k2 = 0; k2 < 2; k2++) {
                        LDSM_X4(bh[k2][0], bh[k2][1], bh[k2][2], bh[k2][3],
                                wHi + SMEM_SWZ(brow * 128 + k2 * 64 + bj));
                        LDSM_X4(bl[k2][0], bl[k2][1], bl[k2][2], bl[k2][3],
                                wLo + SMEM_SWZ(brow * 128 + k2 * 64 + bj));
                    }
#pragma unroll
                    for (int ks = 0; ks < 4; ks++) {
                        int colb = ks * 32 + ac0;
                        uint32_t ah[4], al[4];
                        LDSM_X4(ah[0], ah[1], ah[2], ah[3], hnHi + SMEM_SWZ(arow * 128 + colb));
                        LDSM_X4(al[0], al[1], al[2], al[3], hnLo + SMEM_SWZ(arow * 128 + colb));
                        uint32_t bh0 = bh[ks >> 1][(ks & 1) * 2], bh1 = bh[ks >> 1][(ks & 1) * 2 + 1];
                        uint32_t bl0 = bl[ks >> 1][(ks & 1) * 2], bl1 = bl[ks >> 1][(ks & 1) * 2 + 1];
                        MMA16816(acc, ah, bh0, bh1);
                        MMA16816(acc, ah, bl0, bl1);
                        MMA16816(acc, al, bh0, bh1);
                    }
                }
            }
        }

        // epilogue
        float u00 = xp0.x + acc[0] + bias2.x;
        float u01 = xp0.y + acc[1] + bias2.y;
        float u10 = xp1.x + acc[2] + bias2.x;
        float u11 = xp1.y + acc[3] + bias2.y;
        float h00 = my_tanhf(u00) * mA + hp[0] * (1.f - mA);
        float h01 = my_tanhf(u01) * mA + hp[1] * (1.f - mA);
        float h10 = my_tanhf(u10) * mB + hp[2] * (1.f - mB);
        float h11 = my_tanhf(u11) * mB + hp[3] * (1.f - mB);
        hp[0] = h00; hp[1] = h01; hp[2] = h10; hp[3] = h11;

        int pp = s & 1;
        char* dst = g_hn2 + ((size_t)(dir * 2 + pp) * 4 + bg) * 32768 + (hg >> 1) * 4096;
        float hn00 = h00 * nh0.x, hn01 = h01 * nh0.y;
        float hn10 = h10 * nh1.x, hn11 = h11 * nh1.y;
        __nv_bfloat162 v;
        __nv_bfloat16 c00 = __float2bfloat16(hn00), c01 = __float2bfloat16(hn01);
        __nv_bfloat16 c10 = __float2bfloat16(hn10), c11 = __float2bfloat16(hn11);
        v.x = c00; v.y = c01; *(__nv_bfloat162*)(dst + o0) = v;
        v.x = c10; v.y = c11; *(__nv_bfloat162*)(dst + o1) = v;
        v.x = __float2bfloat16(hn00 - __bfloat162float(c00));
        v.y = __float2bfloat16(hn01 - __bfloat162float(c01));
        *(__nv_bfloat162*)(dst + 2048 + o0) = v;
        v.x = __float2bfloat16(hn10 - __bfloat162float(c10));
        v.y = __float2bfloat16(hn11 - __bfloat162float(c11));
        *(__nv_bfloat162*)(dst + 2048 + o1) = v;

        // per-warp release: warp-local hb then lane0 publishes
        __syncwarp();
        if (lane == 0)
            st_rel(&g_flags[dir][bg][hg][warp][0], fbase + (unsigned)(s + 1));

        // outputs (off the inter-CTA critical path)
        float2 y0; y0.x = h00; y0.y = h01;
        float2 y1; y1.x = h10; y1.y = h11;
        *(float2*)(ys + ((size_t)t * BB + b0) * (2 * HH) + dir * HH + h0) = y0;
        *(float2*)(ys + ((size_t)t * BB + b1) * (2 * HH) + dir * HH + h0) = y1;
        if (s == TT - 1) {
            float* hd = dout + (size_t)TT * BB * 2 * HH + (size_t)cell * BB * HH;
            *(float2*)(hd + b0 * HH + h0) = y0;
            *(float2*)(hd + b1 * HH + h0) = y1;
        }
    }
}

// ---------------------------------------------------------------------------
extern "C" void kernel_launch(void* const* d_in, const int* in_sizes, int n_in,
                              void* d_out, int out_size)
{
    const float* input    = (const float*)d_in[0];
    const float* mask     = (const float*)d_in[1];
    const float* w_ih     = (const float*)d_in[2];
    const float* w_hh     = (const float*)d_in[3];
    const float* b_ih     = (const float*)d_in[4];
    const float* b_hh     = (const float*)d_in[5];
    const float* noise_in = (const float*)d_in[6];
    const float* noise_h  = (const float*)d_in[7];
    float* out = (float*)d_out;

    cudaFuncSetAttribute(proj_mma_kernel, cudaFuncAttributeMaxDynamicSharedMemorySize, PROJ_SMEM);
    cudaFuncSetAttribute(rnn_mma_kernel, cudaFuncAttributeMaxDynamicSharedMemorySize, RNN_SMEM);

    conv_kernel<<<3072, 256>>>(w_ih, w_hh);
    for (int layer = 0; layer < 2; layer++) {
        aconv_kernel<<<32768, 256>>>(input, noise_in, layer);
        proj_mma_kernel<<<dim3(4, 256, 2), 256, PROJ_SMEM>>>(b_ih, layer);
        rnn_mma_kernel<<<dim3(16, 4, 2), 128, RNN_SMEM>>>(b_hh, noise_h, mask, out, layer);
    }
}

// round 14
// speedup vs baseline: 1.3700x; 1.3700x over previous
#include <cuda_runtime.h>
#include <cuda_bf16.h>
#include <cuda_fp16.h>
#include <cstdint>

#define TT 512
#define BB 64
#define HH 512
#define II 1024

// ---- scratch ---------------------------------------------------------------
__device__ float g_xproj[2][(size_t)TT * BB * HH];
__device__ float g_l0out[(size_t)TT * BB * 2 * HH];
__device__ unsigned g_flags[2][4][16][32];   // [dir][bg][hg][128B line]
// proj operands: pre-swizzled fp16 blocks (128 rows x 64 k = 16384B)
__device__ char g_ahi[(size_t)2 * 256 * 16 * 16384];          // A fp16 (single plane)
__device__ char g_whi[(size_t)4 * 4 * 16 * 16384];            // W_ih fp16 hi
__device__ char g_wlo[(size_t)4 * 4 * 16 * 16384];            // W_ih fp16 lo
// recurrence: W_hh bf16 pre-swizzled blocks (16 rows x 64 k = 2048B, 8 chunks)
__device__ char g_whh_hi[(size_t)4 * 32 * 16384];
__device__ char g_whh_lo[(size_t)4 * 32 * 16384];
// h*noise: [dir*2+pp][bg] 32KB block = [kc 8][plane 2][16b x 128B swizzled]
__device__ char g_hn2[(size_t)4 * 4 * 32768];

// ---- helpers ---------------------------------------------------------------
__device__ __forceinline__ unsigned ld_acq(const unsigned* p) {
    unsigned v;
    asm volatile("ld.acquire.gpu.global.u32 %0, [%1];" : "=r"(v) : "l"(p) : "memory");
    return v;
}
__device__ __forceinline__ void st_rel(unsigned* p, unsigned v) {
    asm volatile("st.release.gpu.global.u32 [%0], %1;" :: "l"(p), "r"(v) : "memory");
}
__device__ __forceinline__ float my_tanhf(float x) {
    float e = __expf(2.f * x);
    return 1.f - 2.f / (e + 1.f);
}
__device__ __forceinline__ uint32_t smem_to_u32(const void* p) {
    uint32_t a;
    asm("{ .reg .u64 t; cvta.to.shared.u64 t, %1; cvt.u32.u64 %0, t; }" : "=r"(a) : "l"(p));
    return a;
}
#define CP_ASYNC16(dst, src) \
    asm volatile("cp.async.cg.shared.global [%0], [%1], 16;" :: "r"(dst), "l"(src))
#define CP_COMMIT() asm volatile("cp.async.commit_group;" ::: "memory")
#define CP_WAIT(N)  asm volatile("cp.async.wait_group %0;" :: "n"(N) : "memory")
#define SMEM_SWZ(off) ((off) ^ (((off) >> 3) & 0x70))
#define LDSM_X4(r0, r1, r2, r3, a) \
    asm volatile("ldmatrix.sync.aligned.m8n8.x4.shared.b16 {%0,%1,%2,%3}, [%4];" \
        : "=r"(r0), "=r"(r1), "=r"(r2), "=r"(r3) : "r"(a))
#define MMA16816(c, a, b0, b1) \
    asm volatile("mma.sync.aligned.m16n8k16.row.col.f32.bf16.bf16.f32 " \
        "{%0,%1,%2,%3}, {%4,%5,%6,%7}, {%8,%9}, {%0,%1,%2,%3};" \
        : "+f"((c)[0]), "+f"((c)[1]), "+f"((c)[2]), "+f"((c)[3]) \
        : "r"((a)[0]), "r"((a)[1]), "r"((a)[2]), "r"((a)[3]), "r"(b0), "r"(b1))
#define MMA16816H(c, a, b0, b1) \
    asm volatile("mma.sync.aligned.m16n8k16.row.col.f32.f16.f16.f32 " \
        "{%0,%1,%2,%3}, {%4,%5,%6,%7}, {%8,%9}, {%0,%1,%2,%3};" \
        : "+f"((c)[0]), "+f"((c)[1]), "+f"((c)[2]), "+f"((c)[3]) \
        : "r"((a)[0]), "r"((a)[1]), "r"((a)[2]), "r"((a)[3]), "r"(b0), "r"(b1))

// ---------------------------------------------------------------------------
// Merged weight conversion + one-time flag reset. Blocks [0,2048) = W_ih
// fp16 hi/lo, [2048,3072) = W_hh bf16 hi/lo. Block 0 zeroes the rnn flags.
__global__ __launch_bounds__(256) void conv_kernel(
    const float* __restrict__ w_ih, const float* __restrict__ w_hh)
{
    if (blockIdx.x == 0 && threadIdx.x < 128) {
        ((unsigned*)g_flags)[threadIdx.x * 32] = 0u;   // 2*4*16 flags, 128B apart
    }
    if (blockIdx.x < 2048) {
        int e0 = (blockIdx.x * 256 + threadIdx.x) * 4;
        int cell = e0 >> 19;
        int rem  = e0 & 524287;
        int h = rem >> 10;
        int k = rem & 1023;
        float4 v = *(const float4*)(w_ih + (size_t)e0);
        __half h0 = __float2half(v.x), h1 = __float2half(v.y);
        __half h2 = __float2half(v.z), h3 = __float2half(v.w);
        __half l0 = __float2half(v.x - __half2float(h0));
        __half l1 = __float2half(v.y - __half2float(h1));
        __half l2 = __float2half(v.z - __half2float(h2));
        __half l3 = __float2half(v.w - __half2float(h3));
        int nb = h >> 7, hr = h & 127, kc = k >> 6, kk = k & 63;
        int sw = SMEM_SWZ(hr * 128 + kk * 2);
        size_t base = ((size_t)(cell * 4 + nb) * 16 + kc) * 16384 + sw;
        __half2 p;
        p.x = h0; p.y = h1; *(__half2*)(g_whi + base) = p;
        p.x = h2; p.y = h3; *(__half2*)(g_whi + base + 4) = p;
        p.x = l0; p.y = l1; *(__half2*)(g_wlo + base) = p;
        p.x = l2; p.y = l3; *(__half2*)(g_wlo + base + 4) = p;
    } else {
        int e0 = ((blockIdx.x - 2048) * 256 + threadIdx.x) * 4;
        int cell = e0 >> 18;
        int rem  = e0 & 262143;
        int h = rem >> 9;
        int k = rem & 511;
        float4 v = *(const float4*)(w_hh + (size_t)e0);
        __nv_bfloat16 h0 = __float2bfloat16(v.x), h1 = __float2bfloat16(v.y);
        __nv_bfloat16 h2 = __float2bfloat16(v.z), h3 = __float2bfloat16(v.w);
        __nv_bfloat16 l0 = __float2bfloat16(v.x - __bfloat162float(h0));
        __nv_bfloat16 l1 = __float2bfloat16(v.y - __bfloat162float(h1));
        __nv_bfloat16 l2 = __float2bfloat16(v.z - __bfloat162float(h2));
        __nv_bfloat16 l3 = __float2bfloat16(v.w - __bfloat162float(h3));
        int hg = h >> 4, r = h & 15, kc = k >> 6, kk = k & 63;
        size_t base = (size_t)(cell * 32 + hg) * 16384 + kc * 2048 + SMEM_SWZ(r * 128 + kk * 2);
        __nv_bfloat162 p;
        p.x = h0; p.y = h1; *(__nv_bfloat162*)(g_whh_hi + base) = p;
        p.x = h2; p.y = h3; *(__nv_bfloat162*)(g_whh_hi + base + 4) = p;
        p.x = l0; p.y = l1; *(__nv_bfloat162*)(g_whh_lo + base) = p;
        p.x = l2; p.y = l3; *(__nv_bfloat162*)(g_whh_lo + base + 4) = p;
    }
}

// ---------------------------------------------------------------------------
// A -> fp16 pre-swizzled blocks, both dirs per block (A read once).
__global__ __launch_bounds__(256) void aconv_kernel(
    const float* __restrict__ Ain, const float* __restrict__ nin, int layer)
{
    const float* A = (layer == 0) ? Ain : g_l0out;
    int e0 = (blockIdx.x * 256 + threadIdx.x) * 4;
    int m = e0 >> 10;
    int k = e0 & 1023;
    float4 a = *(const float4*)(A + (size_t)e0);
    int mb = m >> 7, mr = m & 127, kc = k >> 6, kk = k & 63;
    int sw = SMEM_SWZ(mr * 128 + kk * 2);
#pragma unroll
    for (int dir = 0; dir < 2; dir++) {
        int cell = layer * 2 + dir;
        float4 n = *(const float4*)(nin + (size_t)cell * BB * II + (m & 63) * II + k);
        __half2 p0, p1;
        p0.x = __float2half(a.x * n.x); p0.y = __float2half(a.y * n.y);
        p1.x = __float2half(a.z * n.z); p1.y = __float2half(a.w * n.w);
        size_t base = ((size_t)(dir * 256 + mb) * 16 + kc) * 16384 + sw;
        *(__half2*)(g_ahi + base) = p0;
        *(__half2*)(g_ahi + base + 4) = p1;
    }
}

// ---------------------------------------------------------------------------
// proj via mma.sync fp16 2-term (R12 winner, unchanged).
#define PROJ_SMEM 98304

#define PROJ_ISSUE(c) do { \
    uint32_t st = smb + ((c) & 1) * 49152 + tid * 16; \
    size_t go = (size_t)(c) * 16384 + tid * 16; \
    _Pragma("unroll") \
    for (int p = 0; p < 4; p++) { \
        CP_ASYNC16(st +     0 + p * 4096, srcAh + go + p * 4096); \
        CP_ASYNC16(st + 16384 + p * 4096, srcBh + go + p * 4096); \
        CP_ASYNC16(st + 32768 + p * 4096, srcBl + go + p * 4096); \
    } \
    CP_COMMIT(); \
} while (0)

__global__ __launch_bounds__(256, 1) void proj_mma_kernel(
    const float* __restrict__ b_ih, int layer)
{
    extern __shared__ char smc[];
    uint32_t smb = smem_to_u32(smc);
    int tid = threadIdx.x, lane = tid & 31, warp = tid >> 5;
    int nb = blockIdx.x, mb = blockIdx.y, dir = blockIdx.z;
    int cell = layer * 2 + dir;
    const char* srcAh = g_ahi + (size_t)(dir * 256 + mb) * 16 * 16384;
    const char* srcBh = g_whi + (size_t)(cell * 4 + nb) * 16 * 16384;
    const char* srcBl = g_wlo + (size_t)(cell * 4 + nb) * 16 * 16384;

    float acc[2][8][4];
#pragma unroll
    for (int i = 0; i < 2; i++)
#pragma unroll
        for (int j = 0; j < 8; j++)
#pragma unroll
            for (int q = 0; q < 4; q++) acc[i][j][q] = 0.f;

    int wm = (warp >> 1) * 32;
    int wn = (warp & 1) * 64;
    int ar  = wm + (lane & 15);
    int ac0 = (lane >> 4) << 4;
    int br  = wn + ((lane >> 4) << 3) + (lane & 7);
    int bc0 = ((lane >> 3) & 1) << 4;

    PROJ_ISSUE(0);
    for (int c = 0; c < 16; c++) {
        if (c + 1 < 16) { PROJ_ISSUE(c + 1); CP_WAIT(1); }
        else CP_WAIT(0);
        __syncthreads();
        uint32_t st = smb + (c & 1) * 49152;
#pragma unroll
        for (int ks = 0; ks < 4; ks++) {
            int acol = ks * 32 + ac0;
            int bcol = ks * 32 + bc0;
            uint32_t ah[2][4];
            LDSM_X4(ah[0][0], ah[0][1], ah[0][2], ah[0][3], st + SMEM_SWZ(ar * 128 + acol));
            LDSM_X4(ah[1][0], ah[1][1], ah[1][2], ah[1][3], st + SMEM_SWZ((ar + 16) * 128 + acol));
            uint32_t bh[4][4], bl[4][4];
#pragma unroll
            for (int j = 0; j < 4; j++) {
                LDSM_X4(bh[j][0], bh[j][1], bh[j][2], bh[j][3],
                        st + 16384 + SMEM_SWZ((br + j * 16) * 128 + bcol));
                LDSM_X4(bl[j][0], bl[j][1], bl[j][2], bl[j][3],
                        st + 32768 + SMEM_SWZ((br + j * 16) * 128 + bcol));
            }
#pragma unroll
            for (int mt = 0; mt < 2; mt++)
#pragma unroll
                for (int j = 0; j < 4; j++) {
                    MMA16816H(acc[mt][2 * j],     ah[mt], bh[j][0], bh[j][1]);
                    MMA16816H(acc[mt][2 * j],     ah[mt], bl[j][0], bl[j][1]);
                    MMA16816H(acc[mt][2 * j + 1], ah[mt], bh[j][2], bh[j][3]);
                    MMA16816H(acc[mt][2 * j + 1], ah[mt], bl[j][2], bl[j][3]);
                }
        }
        __syncthreads();
    }

    const float* bias = b_ih + (size_t)cell * HH;
    float* out = g_xproj[dir];
    int g  = lane >> 2;
    int tq = (lane & 3) * 2;
    int m0 = mb * 128 + wm;
    int n0 = nb * 128 + wn;
#pragma unroll
    for (int mt = 0; mt < 2; mt++)
#pragma unroll
        for (int nt = 0; nt < 8; nt++) {
            int h = n0 + nt * 8 + tq;
            float2 bi = *(const float2*)(bias + h);
            int m = m0 + mt * 16 + g;
            float2 v;
            v.x = acc[mt][nt][0] + bi.x; v.y = acc[mt][nt][1] + bi.y;
            *(float2*)(out + (size_t)m * HH + h) = v;
            v.x = acc[mt][nt][2] + bi.x; v.y = acc[mt][nt][3] + bi.y;
            *(float2*)(out + (size_t)(m + 8) * HH + h) = v;
        }
}

// ---------------------------------------------------------------------------
// Persistent recurrence (R12 winner: per-CTA flags, 1-warp poll), monotonic
// flag targets. grid (16 hg, 4 bg, 2 dir), 128 threads.
// smem: A stage 32KB | W hi 32KB @32768 | W lo 32KB @65536.
#define RNN_SMEM 98304

__global__ __launch_bounds__(128, 1) void rnn_mma_kernel(
    const float* __restrict__ b_hh, const float* __restrict__ noise_h,
    const float* __restrict__ mask, float* __restrict__ dout, int layer)
{
    extern __shared__ char smc[];
    uint32_t smb = smem_to_u32(smc);
    int tid = threadIdx.x, lane = tid & 31, warp = tid >> 5;   // warp 0..3
    int hg = blockIdx.x, bg = blockIdx.y, dir = blockIdx.z;
    int cell = layer * 2 + dir;
    unsigned fbase = (unsigned)(layer << 9);
    float* ys = (layer == 0) ? g_l0out : dout;
    const float* xproj = g_xproj[dir];

    // one-time: resident W_hh hi/lo (2 contiguous 16KB blocks each)
    {
        const char* wsh = g_whh_hi + (size_t)(cell * 32 + hg * 2) * 16384;
        const char* wsl = g_whh_lo + (size_t)(cell * 32 + hg * 2) * 16384;
#pragma unroll
        for (int i = 0; i < 16; i++) {
            CP_ASYNC16(smb + 32768 + tid * 16 + i * 2048, wsh + tid * 16 + i * 2048);
            CP_ASYNC16(smb + 65536 + tid * 16 + i * 2048, wsl + tid * 16 + i * 2048);
        }
        CP_COMMIT();
        CP_WAIT(0);
        __syncthreads();
    }

    int g  = lane >> 2;
    int tq = (lane & 3) * 2;
    int b0l = g, b1l = g + 8;
    int b0 = bg * 16 + b0l, b1 = bg * 16 + b1l;
    int hl32 = warp * 8 + tq;              // h local in CTA, 0..31
    int h0 = hg * 32 + hl32;

    float2 bias2 = *(const float2*)(b_hh + (size_t)cell * HH + h0);
    float2 nh0 = *(const float2*)(noise_h + ((size_t)cell * BB + b0) * HH + h0);
    float2 nh1 = *(const float2*)(noise_h + ((size_t)cell * BB + b1) * HH + h0);
    float hp[4] = {0.f, 0.f, 0.f, 0.f};

    // fragment addresses (A: 16 batches; B: warp's 8 h rows)
    int arow = lane & 15;
    int ac0  = (lane >> 4) << 4;
    int brow = (warp & 1) * 8 + (lane & 7);
    int bj   = (lane >> 3) << 4;
    uint32_t wb_hi = smb + 32768 + (warp >> 1) * 16384;
    uint32_t wb_lo = wb_hi + 32768;

    // producer hn in-tile offsets: chunk = hg>>1, h within chunk 0..63
    int hl64 = (hg & 1) * 32 + hl32;
    uint32_t o0 = SMEM_SWZ(b0l * 128 + hl64 * 2);
    uint32_t o1 = SMEM_SWZ(b1l * 128 + hl64 * 2);

    for (int s = 0; s < TT; s++) {
        int t = dir ? (TT - 1 - s) : s;
        float2 xp0 = *(const float2*)(xproj + ((size_t)t * BB + b0) * HH + h0);
        float2 xp1 = *(const float2*)(xproj + ((size_t)t * BB + b1) * HH + h0);
        float mA = mask[t * BB + b0];
        float mB = mask[t * BB + b1];

        float acc[4] = {0.f, 0.f, 0.f, 0.f};

        if (s > 0) {
            // wait for the 16 producers of this (dir, bg) — 1 polling warp
            if (tid < 32) {
                const unsigned* fp = &g_flags[dir][bg][lane & 15][0];
                bool mine = lane < 16;
                unsigned tgt = fbase + (unsigned)s;
                unsigned v;
                do { v = mine ? ld_acq(fp) : 0xffffffffu; }
                while (!__all_sync(0xffffffffu, v >= tgt));
            }
            __syncthreads();
            const char* src = g_hn2 + ((size_t)(dir * 2 + ((s + 1) & 1)) * 4 + bg) * 32768;
#pragma unroll
            for (int i = 0; i < 8; i++)
                CP_ASYNC16(smb + tid * 16 + i * 2048, src + tid * 16 + i * 2048);
            CP_COMMIT();
#pragma unroll
            for (int i = 8; i < 16; i++)
                CP_ASYNC16(smb + tid * 16 + i * 2048, src + tid * 16 + i * 2048);
            CP_COMMIT();

#pragma unroll
            for (int gp = 0; gp < 2; gp++) {
                if (gp == 0) CP_WAIT(1);
                else CP_WAIT(0);
                __syncthreads();
#pragma unroll
                for (int ci = 0; ci < 4; ci++) {
                    int kc = gp * 4 + ci;
                    uint32_t hnHi = smb + kc * 4096;
                    uint32_t hnLo = hnHi + 2048;
                    uint32_t wHi  = wb_hi + kc * 2048;
                    uint32_t wLo  = wb_lo + kc * 2048;
                    uint32_t bh[2][4], bl[2][4];
#pragma unroll
                    for (int k2 = 0; k2 < 2; k2++) {
                        LDSM_X4(bh[k2][0], bh[k2][1], bh[k2][2], bh[k2][3],
                                wHi + SMEM_SWZ(brow * 128 + k2 * 64 + bj));
                        LDSM_X4(bl[k2][0], bl[k2][1], bl[k2][2], bl[k2][3],
                                wLo + SMEM_SWZ(brow * 128 + k2 * 64 + bj));
                    }
#pragma unroll
                    for (int ks = 0; ks < 4; ks++) {
                        int colb = ks * 32 + ac0;
                        uint32_t ah[4], al[4];
                        LDSM_X4(ah[0], ah[1], ah[2], ah[3], hnHi + SMEM_SWZ(arow * 128 + colb));
                        LDSM_X4(al[0], al[1], al[2], al[3], hnLo + SMEM_SWZ(arow * 128 + colb));
                        uint32_t bh0 = bh[ks >> 1][(ks & 1) * 2], bh1 = bh[ks >> 1][(ks & 1) * 2 + 1];
                        uint32_t bl0 = bl[ks >> 1][(ks & 1) * 2], bl1 = bl[ks >> 1][(ks & 1) * 2 + 1];
                        MMA16816(acc, ah, bh0, bh1);
                        MMA16816(acc, ah, bl0, bl1);
                        MMA16816(acc, al, bh0, bh1);
                    }
                }
            }
        }

        // epilogue
        float u00 = xp0.x + acc[0] + bias2.x;
        float u01 = xp0.y + acc[1] + bias2.y;
        float u10 = xp1.x + acc[2] + bias2.x;
        float u11 = xp1.y + acc[3] + bias2.y;
        float h00 = my_tanhf(u00) * mA + hp[0] * (1.f - mA);
        float h01 = my_tanhf(u01) * mA + hp[1] * (1.f - mA);
        float h10 = my_tanhf(u10) * mB + hp[2] * (1.f - mB);
        float h11 = my_tanhf(u11) * mB + hp[3] * (1.f - mB);
        hp[0] = h00; hp[1] = h01; hp[2] = h10; hp[3] = h11;

        int pp = s & 1;
        char* dst = g_hn2 + ((size_t)(dir * 2 + pp) * 4 + bg) * 32768 + (hg >> 1) * 4096;
        float hn00 = h00 * nh0.x, hn01 = h01 * nh0.y;
        float hn10 = h10 * nh1.x, hn11 = h11 * nh1.y;
        __nv_bfloat162 v;
        __nv_bfloat16 c00 = __float2bfloat16(hn00), c01 = __float2bfloat16(hn01);
        __nv_bfloat16 c10 = __float2bfloat16(hn10), c11 = __float2bfloat16(hn11);
        v.x = c00; v.y = c01; *(__nv_bfloat162*)(dst + o0) = v;
        v.x = c10; v.y = c11; *(__nv_bfloat162*)(dst + o1) = v;
        v.x = __float2bfloat16(hn00 - __bfloat162float(c00));
        v.y = __float2bfloat16(hn01 - __bfloat162float(c01));
        *(__nv_bfloat162*)(dst + 2048 + o0) = v;
        v.x = __float2bfloat16(hn10 - __bfloat162float(c10));
        v.y = __float2bfloat16(hn11 - __bfloat162float(c11));
        *(__nv_bfloat162*)(dst + 2048 + o1) = v;

        __syncthreads();
        if (tid == 0) st_rel(&g_flags[dir][bg][hg][0], fbase + (unsigned)(s + 1));

        // outputs (off the inter-CTA critical path)
        float2 y0; y0.x = h00; y0.y = h01;
        float2 y1; y1.x = h10; y1.y = h11;
        *(float2*)(ys + ((size_t)t * BB + b0) * (2 * HH) + dir * HH + h0) = y0;
        *(float2*)(ys + ((size_t)t * BB + b1) * (2 * HH) + dir * HH + h0) = y1;
        if (s == TT - 1) {
            float* hd = dout + (size_t)TT * BB * 2 * HH + (size_t)cell * BB * HH;
            *(float2*)(hd + b0 * HH + h0) = y0;
            *(float2*)(hd + b1 * HH + h0) = y1;
        }
    }
}

// ---------------------------------------------------------------------------
extern "C" void kernel_launch(void* const* d_in, const int* in_sizes, int n_in,
                              void* d_out, int out_size)
{
    const float* input    = (const float*)d_in[0];
    const float* mask     = (const float*)d_in[1];
    const float* w_ih     = (const float*)d_in[2];
    const float* w_hh     = (const float*)d_in[3];
    const float* b_ih     = (const float*)d_in[4];
    const float* b_hh     = (const float*)d_in[5];
    const float* noise_in = (const float*)d_in[6];
    const float* noise_h  = (const float*)d_in[7];
    float* out = (float*)d_out;

    cudaFuncSetAttribute(proj_mma_kernel, cudaFuncAttributeMaxDynamicSharedMemorySize, PROJ_SMEM);
    cudaFuncSetAttribute(rnn_mma_kernel, cudaFuncAttributeMaxDynamicSharedMemorySize, RNN_SMEM);

    conv_kernel<<<3072, 256>>>(w_ih, w_hh);
    for (int layer = 0; layer < 2; layer++) {
        aconv_kernel<<<32768, 256>>>(input, noise_in, layer);
        proj_mma_kernel<<<dim3(4, 256, 2), 256, PROJ_SMEM>>>(b_ih, layer);
        rnn_mma_kernel<<<dim3(16, 4, 2), 128, RNN_SMEM>>>(b_hh, noise_h, mask, out, layer);
    }
}

// round 15
// speedup vs baseline: 1.3875x; 1.0128x over previous
#include <cuda_runtime.h>
#include <cuda_bf16.h>
#include <cuda_fp16.h>
#include <cstdint>

#define TT 512
#define BB 64
#define HH 512
#define II 1024

// ---- scratch ---------------------------------------------------------------
__device__ float g_xproj[2][(size_t)TT * BB * HH];
__device__ float g_l0out[(size_t)TT * BB * 2 * HH];
__device__ unsigned g_flags[2][4][16][32];   // [dir][bg][hg][128B line]
// proj operands: pre-swizzled fp16 blocks (128 rows x 64 k = 16384B)
__device__ char g_ahi[(size_t)2 * 256 * 16 * 16384];          // A fp16 (single plane)
__device__ char g_whi[(size_t)4 * 4 * 16 * 16384];            // W_ih fp16 hi
__device__ char g_wlo[(size_t)4 * 4 * 16 * 16384];            // W_ih fp16 lo
// recurrence: W_hh bf16 pre-swizzled blocks (16 rows x 64 k = 2048B, 8 chunks)
__device__ char g_whh_hi[(size_t)4 * 32 * 16384];
__device__ char g_whh_lo[(size_t)4 * 32 * 16384];
// h*noise: [dir*2+pp][bg] 32KB block = [kc 8][plane 2][16b x 128B swizzled]
__device__ char g_hn2[(size_t)4 * 4 * 32768];

// ---- helpers ---------------------------------------------------------------
__device__ __forceinline__ unsigned ld_acq(const unsigned* p) {
    unsigned v;
    asm volatile("ld.acquire.gpu.global.u32 %0, [%1];" : "=r"(v) : "l"(p) : "memory");
    return v;
}
__device__ __forceinline__ void st_rel(unsigned* p, unsigned v) {
    asm volatile("st.release.gpu.global.u32 [%0], %1;" :: "l"(p), "r"(v) : "memory");
}
__device__ __forceinline__ float my_tanhf(float x) {
    float e = __expf(2.f * x);
    return 1.f - 2.f / (e + 1.f);
}
__device__ __forceinline__ uint32_t smem_to_u32(const void* p) {
    uint32_t a;
    asm("{ .reg .u64 t; cvta.to.shared.u64 t, %1; cvt.u32.u64 %0, t; }" : "=r"(a) : "l"(p));
    return a;
}
#define CP_ASYNC16(dst, src) \
    asm volatile("cp.async.cg.shared.global [%0], [%1], 16;" :: "r"(dst), "l"(src))
#define CP_COMMIT() asm volatile("cp.async.commit_group;" ::: "memory")
#define CP_WAIT(N)  asm volatile("cp.async.wait_group %0;" :: "n"(N) : "memory")
#define SMEM_SWZ(off) ((off) ^ (((off) >> 3) & 0x70))
#define LDSM_X4(r0, r1, r2, r3, a) \
    asm volatile("ldmatrix.sync.aligned.m8n8.x4.shared.b16 {%0,%1,%2,%3}, [%4];" \
        : "=r"(r0), "=r"(r1), "=r"(r2), "=r"(r3) : "r"(a))
#define MMA16816(c, a, b0, b1) \
    asm volatile("mma.sync.aligned.m16n8k16.row.col.f32.bf16.bf16.f32 " \
        "{%0,%1,%2,%3}, {%4,%5,%6,%7}, {%8,%9}, {%0,%1,%2,%3};" \
        : "+f"((c)[0]), "+f"((c)[1]), "+f"((c)[2]), "+f"((c)[3]) \
        : "r"((a)[0]), "r"((a)[1]), "r"((a)[2]), "r"((a)[3]), "r"(b0), "r"(b1))
#define MMA16816H(c, a, b0, b1) \
    asm volatile("mma.sync.aligned.m16n8k16.row.col.f32.f16.f16.f32 " \
        "{%0,%1,%2,%3}, {%4,%5,%6,%7}, {%8,%9}, {%0,%1,%2,%3};" \
        : "+f"((c)[0]), "+f"((c)[1]), "+f"((c)[2]), "+f"((c)[3]) \
        : "r"((a)[0]), "r"((a)[1]), "r"((a)[2]), "r"((a)[3]), "r"(b0), "r"(b1))

// ---------------------------------------------------------------------------
// Merged weight conversion + one-time flag reset.
__global__ __launch_bounds__(256) void conv_kernel(
    const float* __restrict__ w_ih, const float* __restrict__ w_hh)
{
    if (blockIdx.x == 0 && threadIdx.x < 128) {
        ((unsigned*)g_flags)[threadIdx.x * 32] = 0u;   // 2*4*16 flags, 128B apart
    }
    if (blockIdx.x < 2048) {
        int e0 = (blockIdx.x * 256 + threadIdx.x) * 4;
        int cell = e0 >> 19;
        int rem  = e0 & 524287;
        int h = rem >> 10;
        int k = rem & 1023;
        float4 v = *(const float4*)(w_ih + (size_t)e0);
        __half h0 = __float2half(v.x), h1 = __float2half(v.y);
        __half h2 = __float2half(v.z), h3 = __float2half(v.w);
        __half l0 = __float2half(v.x - __half2float(h0));
        __half l1 = __float2half(v.y - __half2float(h1));
        __half l2 = __float2half(v.z - __half2float(h2));
        __half l3 = __float2half(v.w - __half2float(h3));
        int nb = h >> 7, hr = h & 127, kc = k >> 6, kk = k & 63;
        int sw = SMEM_SWZ(hr * 128 + kk * 2);
        size_t base = ((size_t)(cell * 4 + nb) * 16 + kc) * 16384 + sw;
        __half2 p;
        p.x = h0; p.y = h1; *(__half2*)(g_whi + base) = p;
        p.x = h2; p.y = h3; *(__half2*)(g_whi + base + 4) = p;
        p.x = l0; p.y = l1; *(__half2*)(g_wlo + base) = p;
        p.x = l2; p.y = l3; *(__half2*)(g_wlo + base + 4) = p;
    } else {
        int e0 = ((blockIdx.x - 2048) * 256 + threadIdx.x) * 4;
        int cell = e0 >> 18;
        int rem  = e0 & 262143;
        int h = rem >> 9;
        int k = rem & 511;
        float4 v = *(const float4*)(w_hh + (size_t)e0);
        __nv_bfloat16 h0 = __float2bfloat16(v.x), h1 = __float2bfloat16(v.y);
        __nv_bfloat16 h2 = __float2bfloat16(v.z), h3 = __float2bfloat16(v.w);
        __nv_bfloat16 l0 = __float2bfloat16(v.x - __bfloat162float(h0));
        __nv_bfloat16 l1 = __float2bfloat16(v.y - __bfloat162float(h1));
        __nv_bfloat16 l2 = __float2bfloat16(v.z - __bfloat162float(h2));
        __nv_bfloat16 l3 = __float2bfloat16(v.w - __bfloat162float(h3));
        int hg = h >> 4, r = h & 15, kc = k >> 6, kk = k & 63;
        size_t base = (size_t)(cell * 32 + hg) * 16384 + kc * 2048 + SMEM_SWZ(r * 128 + kk * 2);
        __nv_bfloat162 p;
        p.x = h0; p.y = h1; *(__nv_bfloat162*)(g_whh_hi + base) = p;
        p.x = h2; p.y = h3; *(__nv_bfloat162*)(g_whh_hi + base + 4) = p;
        p.x = l0; p.y = l1; *(__nv_bfloat162*)(g_whh_lo + base) = p;
        p.x = l2; p.y = l3; *(__nv_bfloat162*)(g_whh_lo + base + 4) = p;
    }
}

// ---------------------------------------------------------------------------
// A -> fp16 pre-swizzled blocks, both dirs per block (A read once).
__global__ __launch_bounds__(256) void aconv_kernel(
    const float* __restrict__ Ain, const float* __restrict__ nin, int layer)
{
    const float* A = (layer == 0) ? Ain : g_l0out;
    int e0 = (blockIdx.x * 256 + threadIdx.x) * 4;
    int m = e0 >> 10;
    int k = e0 & 1023;
    float4 a = *(const float4*)(A + (size_t)e0);
    int mb = m >> 7, mr = m & 127, kc = k >> 6, kk = k & 63;
    int sw = SMEM_SWZ(mr * 128 + kk * 2);
#pragma unroll
    for (int dir = 0; dir < 2; dir++) {
        int cell = layer * 2 + dir;
        float4 n = *(const float4*)(nin + (size_t)cell * BB * II + (m & 63) * II + k);
        __half2 p0, p1;
        p0.x = __float2half(a.x * n.x); p0.y = __float2half(a.y * n.y);
        p1.x = __float2half(a.z * n.z); p1.y = __float2half(a.w * n.w);
        size_t base = ((size_t)(dir * 256 + mb) * 16 + kc) * 16384 + sw;
        *(__half2*)(g_ahi + base) = p0;
        *(__half2*)(g_ahi + base + 4) = p1;
    }
}

// ---------------------------------------------------------------------------
// proj via mma.sync fp16 2-term (unchanged).
#define PROJ_SMEM 98304

#define PROJ_ISSUE(c) do { \
    uint32_t st = smb + ((c) & 1) * 49152 + tid * 16; \
    size_t go = (size_t)(c) * 16384 + tid * 16; \
    _Pragma("unroll") \
    for (int p = 0; p < 4; p++) { \
        CP_ASYNC16(st +     0 + p * 4096, srcAh + go + p * 4096); \
        CP_ASYNC16(st + 16384 + p * 4096, srcBh + go + p * 4096); \
        CP_ASYNC16(st + 32768 + p * 4096, srcBl + go + p * 4096); \
    } \
    CP_COMMIT(); \
} while (0)

__global__ __launch_bounds__(256, 1) void proj_mma_kernel(
    const float* __restrict__ b_ih, int layer)
{
    extern __shared__ char smc[];
    uint32_t smb = smem_to_u32(smc);
    int tid = threadIdx.x, lane = tid & 31, warp = tid >> 5;
    int nb = blockIdx.x, mb = blockIdx.y, dir = blockIdx.z;
    int cell = layer * 2 + dir;
    const char* srcAh = g_ahi + (size_t)(dir * 256 + mb) * 16 * 16384;
    const char* srcBh = g_whi + (size_t)(cell * 4 + nb) * 16 * 16384;
    const char* srcBl = g_wlo + (size_t)(cell * 4 + nb) * 16 * 16384;

    float acc[2][8][4];
#pragma unroll
    for (int i = 0; i < 2; i++)
#pragma unroll
        for (int j = 0; j < 8; j++)
#pragma unroll
            for (int q = 0; q < 4; q++) acc[i][j][q] = 0.f;

    int wm = (warp >> 1) * 32;
    int wn = (warp & 1) * 64;
    int ar  = wm + (lane & 15);
    int ac0 = (lane >> 4) << 4;
    int br  = wn + ((lane >> 4) << 3) + (lane & 7);
    int bc0 = ((lane >> 3) & 1) << 4;

    PROJ_ISSUE(0);
    for (int c = 0; c < 16; c++) {
        if (c + 1 < 16) { PROJ_ISSUE(c + 1); CP_WAIT(1); }
        else CP_WAIT(0);
        __syncthreads();
        uint32_t st = smb + (c & 1) * 49152;
#pragma unroll
        for (int ks = 0; ks < 4; ks++) {
            int acol = ks * 32 + ac0;
            int bcol = ks * 32 + bc0;
            uint32_t ah[2][4];
            LDSM_X4(ah[0][0], ah[0][1], ah[0][2], ah[0][3], st + SMEM_SWZ(ar * 128 + acol));
            LDSM_X4(ah[1][0], ah[1][1], ah[1][2], ah[1][3], st + SMEM_SWZ((ar + 16) * 128 + acol));
            uint32_t bh[4][4], bl[4][4];
#pragma unroll
            for (int j = 0; j < 4; j++) {
                LDSM_X4(bh[j][0], bh[j][1], bh[j][2], bh[j][3],
                        st + 16384 + SMEM_SWZ((br + j * 16) * 128 + bcol));
                LDSM_X4(bl[j][0], bl[j][1], bl[j][2], bl[j][3],
                        st + 32768 + SMEM_SWZ((br + j * 16) * 128 + bcol));
            }
#pragma unroll
            for (int mt = 0; mt < 2; mt++)
#pragma unroll
                for (int j = 0; j < 4; j++) {
                    MMA16816H(acc[mt][2 * j],     ah[mt], bh[j][0], bh[j][1]);
                    MMA16816H(acc[mt][2 * j],     ah[mt], bl[j][0], bl[j][1]);
                    MMA16816H(acc[mt][2 * j + 1], ah[mt], bh[j][2], bh[j][3]);
                    MMA16816H(acc[mt][2 * j + 1], ah[mt], bl[j][2], bl[j][3]);
                }
        }
        __syncthreads();
    }

    const float* bias = b_ih + (size_t)cell * HH;
    float* out = g_xproj[dir];
    int g  = lane >> 2;
    int tq = (lane & 3) * 2;
    int m0 = mb * 128 + wm;
    int n0 = nb * 128 + wn;
#pragma unroll
    for (int mt = 0; mt < 2; mt++)
#pragma unroll
        for (int nt = 0; nt < 8; nt++) {
            int h = n0 + nt * 8 + tq;
            float2 bi = *(const float2*)(bias + h);
            int m = m0 + mt * 16 + g;
            float2 v;
            v.x = acc[mt][nt][0] + bi.x; v.y = acc[mt][nt][1] + bi.y;
            *(float2*)(out + (size_t)m * HH + h) = v;
            v.x = acc[mt][nt][2] + bi.x; v.y = acc[mt][nt][3] + bi.y;
            *(float2*)(out + (size_t)(m + 8) * HH + h) = v;
        }
}

// ---------------------------------------------------------------------------
// Persistent recurrence. Asymmetric staging groups (8KB + 24KB) + deferred
// output stores (hidden in next step's flight window).
// grid (16 hg, 4 bg, 2 dir), 128 threads.
// smem: A stage 32KB | W hi 32KB @32768 | W lo 32KB @65536.
#define RNN_SMEM 98304

#define RNN_CHUNK(kc) do { \
    uint32_t hnHi = smb + (kc) * 4096; \
    uint32_t hnLo = hnHi + 2048; \
    uint32_t wHi  = wb_hi + (kc) * 2048; \
    uint32_t wLo  = wb_lo + (kc) * 2048; \
    uint32_t bh[2][4], bl[2][4]; \
    _Pragma("unroll") \
    for (int k2 = 0; k2 < 2; k2++) { \
        LDSM_X4(bh[k2][0], bh[k2][1], bh[k2][2], bh[k2][3], \
                wHi + SMEM_SWZ(brow * 128 + k2 * 64 + bj)); \
        LDSM_X4(bl[k2][0], bl[k2][1], bl[k2][2], bl[k2][3], \
                wLo + SMEM_SWZ(brow * 128 + k2 * 64 + bj)); \
    } \
    _Pragma("unroll") \
    for (int ks = 0; ks < 4; ks++) { \
        int colb = ks * 32 + ac0; \
        uint32_t ah[4], al[4]; \
        LDSM_X4(ah[0], ah[1], ah[2], ah[3], hnHi + SMEM_SWZ(arow * 128 + colb)); \
        LDSM_X4(al[0], al[1], al[2], al[3], hnLo + SMEM_SWZ(arow * 128 + colb)); \
        uint32_t bh0 = bh[ks >> 1][(ks & 1) * 2], bh1 = bh[ks >> 1][(ks & 1) * 2 + 1]; \
        uint32_t bl0 = bl[ks >> 1][(ks & 1) * 2], bl1 = bl[ks >> 1][(ks & 1) * 2 + 1]; \
        MMA16816(acc, ah, bh0, bh1); \
        MMA16816(acc, ah, bl0, bl1); \
        MMA16816(acc, al, bh0, bh1); \
    } \
} while (0)

__global__ __launch_bounds__(128, 1) void rnn_mma_kernel(
    const float* __restrict__ b_hh, const float* __restrict__ noise_h,
    const float* __restrict__ mask, float* __restrict__ dout, int layer)
{
    extern __shared__ char smc[];
    uint32_t smb = smem_to_u32(smc);
    int tid = threadIdx.x, lane = tid & 31, warp = tid >> 5;
    int hg = blockIdx.x, bg = blockIdx.y, dir = blockIdx.z;
    int cell = layer * 2 + dir;
    unsigned fbase = (unsigned)(layer << 9);
    float* ys = (layer == 0) ? g_l0out : dout;
    const float* xproj = g_xproj[dir];

    // one-time: resident W_hh hi/lo
    {
        const char* wsh = g_whh_hi + (size_t)(cell * 32 + hg * 2) * 16384;
        const char* wsl = g_whh_lo + (size_t)(cell * 32 + hg * 2) * 16384;
#pragma unroll
        for (int i = 0; i < 16; i++) {
            CP_ASYNC16(smb + 32768 + tid * 16 + i * 2048, wsh + tid * 16 + i * 2048);
            CP_ASYNC16(smb + 65536 + tid * 16 + i * 2048, wsl + tid * 16 + i * 2048);
        }
        CP_COMMIT();
        CP_WAIT(0);
        __syncthreads();
    }

    int g  = lane >> 2;
    int tq = (lane & 3) * 2;
    int b0l = g, b1l = g + 8;
    int b0 = bg * 16 + b0l, b1 = bg * 16 + b1l;
    int hl32 = warp * 8 + tq;
    int h0 = hg * 32 + hl32;

    float2 bias2 = *(const float2*)(b_hh + (size_t)cell * HH + h0);
    float2 nh0 = *(const float2*)(noise_h + ((size_t)cell * BB + b0) * HH + h0);
    float2 nh1 = *(const float2*)(noise_h + ((size_t)cell * BB + b1) * HH + h0);
    float hp[4] = {0.f, 0.f, 0.f, 0.f};

    int arow = lane & 15;
    int ac0  = (lane >> 4) << 4;
    int brow = (warp & 1) * 8 + (lane & 7);
    int bj   = (lane >> 3) << 4;
    uint32_t wb_hi = smb + 32768 + (warp >> 1) * 16384;
    uint32_t wb_lo = wb_hi + 32768;

    int hl64 = (hg & 1) * 32 + hl32;
    uint32_t o0 = SMEM_SWZ(b0l * 128 + hl64 * 2);
    uint32_t o1 = SMEM_SWZ(b1l * 128 + hl64 * 2);

    float2 y0d, y1d;                 // deferred outputs
    y0d.x = 0.f; y0d.y = 0.f; y1d = y0d;

    for (int s = 0; s < TT; s++) {
        int t = dir ? (TT - 1 - s) : s;
        float2 xp0 = *(const float2*)(xproj + ((size_t)t * BB + b0) * HH + h0);
        float2 xp1 = *(const float2*)(xproj + ((size_t)t * BB + b1) * HH + h0);
        float mA = mask[t * BB + b0];
        float mB = mask[t * BB + b1];

        float acc[4] = {0.f, 0.f, 0.f, 0.f};

        if (s > 0) {
            // wait for the 16 producers of this (dir, bg) — 1 polling warp
            if (tid < 32) {
                const unsigned* fp = &g_flags[dir][bg][lane & 15][0];
                bool mine = lane < 16;
                unsigned tgt = fbase + (unsigned)s;
                unsigned v;
                do { v = mine ? ld_acq(fp) : 0xffffffffu; }
                while (!__all_sync(0xffffffffu, v >= tgt));
            }
            __syncthreads();
            const char* src = g_hn2 + ((size_t)(dir * 2 + ((s + 1) & 1)) * 4 + bg) * 32768;
            // group 1: chunks 0-1 (8KB)
#pragma unroll
            for (int i = 0; i < 4; i++)
                CP_ASYNC16(smb + tid * 16 + i * 2048, src + tid * 16 + i * 2048);
            CP_COMMIT();
            // group 2: chunks 2-7 (24KB)
#pragma unroll
            for (int i = 4; i < 16; i++)
                CP_ASYNC16(smb + tid * 16 + i * 2048, src + tid * 16 + i * 2048);
            CP_COMMIT();

            // deferred output store of previous step (hidden under flight)
            {
                int tp = dir ? (TT - s) : (s - 1);
                *(float2*)(ys + ((size_t)tp * BB + b0) * (2 * HH) + dir * HH + h0) = y0d;
                *(float2*)(ys + ((size_t)tp * BB + b1) * (2 * HH) + dir * HH + h0) = y1d;
            }

            CP_WAIT(1);
            __syncthreads();
            RNN_CHUNK(0);
            RNN_CHUNK(1);
            CP_WAIT(0);
            __syncthreads();
#pragma unroll
            for (int kc = 2; kc < 8; kc++) RNN_CHUNK(kc);
        }

        // epilogue
        float u00 = xp0.x + acc[0] + bias2.x;
        float u01 = xp0.y + acc[1] + bias2.y;
        float u10 = xp1.x + acc[2] + bias2.x;
        float u11 = xp1.y + acc[3] + bias2.y;
        float h00 = my_tanhf(u00) * mA + hp[0] * (1.f - mA);
        float h01 = my_tanhf(u01) * mA + hp[1] * (1.f - mA);
        float h10 = my_tanhf(u10) * mB + hp[2] * (1.f - mB);
        float h11 = my_tanhf(u11) * mB + hp[3] * (1.f - mB);
        hp[0] = h00; hp[1] = h01; hp[2] = h10; hp[3] = h11;

        int pp = s & 1;
        char* dst = g_hn2 + ((size_t)(dir * 2 + pp) * 4 + bg) * 32768 + (hg >> 1) * 4096;
        float hn00 = h00 * nh0.x, hn01 = h01 * nh0.y;
        float hn10 = h10 * nh1.x, hn11 = h11 * nh1.y;
        __nv_bfloat162 v;
        __nv_bfloat16 c00 = __float2bfloat16(hn00), c01 = __float2bfloat16(hn01);
        __nv_bfloat16 c10 = __float2bfloat16(hn10), c11 = __float2bfloat16(hn11);
        v.x = c00; v.y = c01; *(__nv_bfloat162*)(dst + o0) = v;
        v.x = c10; v.y = c11; *(__nv_bfloat162*)(dst + o1) = v;
        v.x = __float2bfloat16(hn00 - __bfloat162float(c00));
        v.y = __float2bfloat16(hn01 - __bfloat162float(c01));
        *(__nv_bfloat162*)(dst + 2048 + o0) = v;
        v.x = __float2bfloat16(hn10 - __bfloat162float(c10));
        v.y = __float2bfloat16(hn11 - __bfloat162float(c11));
        *(__nv_bfloat162*)(dst + 2048 + o1) = v;

        __syncthreads();
        if (tid == 0) st_rel(&g_flags[dir][bg][hg][0], fbase + (unsigned)(s + 1));

        if (s == TT - 1) {
            // final step: store directly (no next flight window)
            float2 y0; y0.x = h00; y0.y = h01;
            float2 y1; y1.x = h10; y1.y = h11;
            *(float2*)(ys + ((size_t)t * BB + b0) * (2 * HH) + dir * HH + h0) = y0;
            *(float2*)(ys + ((size_t)t * BB + b1) * (2 * HH) + dir * HH + h0) = y1;
            float* hd = dout + (size_t)TT * BB * 2 * HH + (size_t)cell * BB * HH;
            *(float2*)(hd + b0 * HH + h0) = y0;
            *(float2*)(hd + b1 * HH + h0) = y1;
        } else {
            y0d.x = h00; y0d.y = h01;
            y1d.x = h10; y1d.y = h11;
        }
    }
}

// ---------------------------------------------------------------------------
extern "C" void kernel_launch(void* const* d_in, const int* in_sizes, int n_in,
                              void* d_out, int out_size)
{
    const float* input    = (const float*)d_in[0];
    const float* mask     = (const float*)d_in[1];
    const float* w_ih     = (const float*)d_in[2];
    const float* w_hh     = (const float*)d_in[3];
    const float* b_ih     = (const float*)d_in[4];
    const float* b_hh     = (const float*)d_in[5];
    const float* noise_in = (const float*)d_in[6];
    const float* noise_h  = (const float*)d_in[7];
    float* out = (float*)d_out;

    cudaFuncSetAttribute(proj_mma_kernel, cudaFuncAttributeMaxDynamicSharedMemorySize, PROJ_SMEM);
    cudaFuncSetAttribute(rnn_mma_kernel, cudaFuncAttributeMaxDynamicSharedMemorySize, RNN_SMEM);

    conv_kernel<<<3072, 256>>>(w_ih, w_hh);
    for (int layer = 0; layer < 2; layer++) {
        aconv_kernel<<<32768, 256>>>(input, noise_in, layer);
        proj_mma_kernel<<<dim3(4, 256, 2), 256, PROJ_SMEM>>>(b_ih, layer);
        rnn_mma_kernel<<<dim3(16, 4, 2), 128, RNN_SMEM>>>(b_hh, noise_h, mask, out, layer);
    }
}